// round 9
// baseline (speedup 1.0000x reference)
#include <cuda_runtime.h>
#include <cuda_fp16.h>

// Sinkhorn on s[B=32, N=1024, M=1024], MAX_ITER=15, EPS=1e-4.
//
// Single persistent kernel. Factored form s_t = r_i * s0_ij * c_j.
// Block k of batch b owns rows [64k, 64k+64) for ALL phases, so the fp16
// copy of its slice is block-private. Cross-block data is only the 4KB
// column-partial vector per block per column iteration (double-buffered),
// synchronized by a batch-local (16-block) monotonic barrier.
// r lives in block smem; c is redundantly recomputed into every block's
// smem from the partials (identical fixed-order arithmetic in all blocks).
// Finalize reads the fp16 copy (L2-hot) instead of the fp32 input.

#define BB 32
#define NN 1024
#define MM 1024
#define EPSF 1e-4f
#define KB_ 16            // blocks per batch
#define RPB (NN / KB_)    // 64 rows per block

__device__ __half2 g_h[(size_t)BB * NN * MM / 2];           // 64 MB fp16 copy
__device__ float g_part[2][BB * KB_ * MM];                  // double-buffered
__device__ int g_cnt2[BB];                                  // zero-init
__device__ int g_flag[BB];                                  // monotonic, persists

// ---------------------------------------------------------------------------
// Batch-local barrier: 16 blocks of batch b. Monotonic target continues from
// the persisted flag value, so graph replays need no reset.
__device__ __forceinline__ void batch_barrier(int b, int& nextv) {
    __threadfence();          // make this thread's prior global writes visible
    __syncthreads();
    nextv += 1;
    if (threadIdx.x == 0) {
        int old = atomicAdd(&g_cnt2[b], 1);
        if (old == KB_ - 1) {
            atomicExch(&g_cnt2[b], 0);
            __threadfence();
            *(volatile int*)&g_flag[b] = nextv;
        } else {
            while (*(volatile int*)&g_flag[b] - nextv < 0) __nanosleep(32);
        }
        __threadfence();
    }
    __syncthreads();
}

// ---------------------------------------------------------------------------
__global__ void __launch_bounds__(256, 4)
sinkhorn_kernel(const float* __restrict__ s, float* __restrict__ out) {
    const int bx = blockIdx.x;
    const int b = bx >> 4;        // batch
    const int k = bx & (KB_ - 1); // block within batch
    const int tid = threadIdx.x;
    const int i0 = k * RPB;       // first owned row

    __shared__ float sc[MM];      // column scaling c (full vector)
    __shared__ float sr[RPB];     // row scaling r (own rows only)

    // Monotonic barrier base: flag only advances at barriers, and no barrier
    // completes until every block has read its base, so all reads agree.
    int nextv = *(volatile int*)&g_flag[b];

    const size_t row0 = (size_t)(b * NN + i0);

    // ---------------- it = 0: fp32->fp16 conversion + column partials (r=1)
    {
        const float4* sp = (const float4*)(s + row0 * MM) + tid;
        __half2* hp = g_h + row0 * (MM / 2) + tid * 2;
        float4 acc = make_float4(0.f, 0.f, 0.f, 0.f);
#pragma unroll 4
        for (int i = 0; i < RPB; i++) {
            float4 v = __ldcs(sp + (size_t)i * (MM / 4));  // stream fp32
            __half2 h0 = __floats2half2_rn(v.x, v.y);
            __half2 h1 = __floats2half2_rn(v.z, v.w);
            uint2 o;
            o.x = *(unsigned*)&h0;
            o.y = *(unsigned*)&h1;
            *(uint2*)(hp + (size_t)i * (MM / 2)) = o;
            acc.x += v.x; acc.y += v.y; acc.z += v.z; acc.w += v.w;
        }
        *(float4*)&g_part[0][((size_t)(b * KB_ + k)) * MM + tid * 4] = acc;
    }
    batch_barrier(b, nextv);

    // Reduce partials (buffer 0) -> c, c_old = 1. All blocks redundantly.
    {
        const int j = tid * 4;
        float4 p = make_float4(0.f, 0.f, 0.f, 0.f);
#pragma unroll
        for (int q = 0; q < KB_; q++) {
            const float4 v = __ldcg(
                (const float4*)&g_part[0][((size_t)(b * KB_ + q)) * MM + j]);
            p.x += v.x; p.y += v.y; p.z += v.z; p.w += v.w;
        }
        sc[j + 0] = 1.0f / (p.x + EPSF);
        sc[j + 1] = 1.0f / (p.y + EPSF);
        sc[j + 2] = 1.0f / (p.z + EPSF);
        sc[j + 3] = 1.0f / (p.w + EPSF);
    }
    __syncthreads();

    // ---------------- 7 x (row step it=2h+1, col step it=2h+2)
    const int warp = tid >> 5;
    const int lane = tid & 31;

    for (int half = 0; half < 7; half++) {
        // ---- row step: Q_i = sum_j h_ij * c_j ; r_i <- r_old/(r_old*Q+eps)
#pragma unroll
        for (int rr = 0; rr < RPB / 8; rr++) {   // 8 rows per warp
            const int i = warp * (RPB / 8) + rr;
            const uint4* hp =
                (const uint4*)(g_h + (row0 + i) * (MM / 2));
            float acc = 0.f;
#pragma unroll
            for (int kk = 0; kk < 4; kk++) {
                int v4 = kk * 32 + lane;
                uint4 v = hp[v4];
                int jj = v4 * 8;
                float2 f0 = __half22float2(*(__half2*)&v.x);
                float2 f1 = __half22float2(*(__half2*)&v.y);
                float2 f2 = __half22float2(*(__half2*)&v.z);
                float2 f3 = __half22float2(*(__half2*)&v.w);
                acc = fmaf(f0.x, sc[jj + 0], acc);
                acc = fmaf(f0.y, sc[jj + 1], acc);
                acc = fmaf(f1.x, sc[jj + 2], acc);
                acc = fmaf(f1.y, sc[jj + 3], acc);
                acc = fmaf(f2.x, sc[jj + 4], acc);
                acc = fmaf(f2.y, sc[jj + 5], acc);
                acc = fmaf(f3.x, sc[jj + 6], acc);
                acc = fmaf(f3.y, sc[jj + 7], acc);
            }
#pragma unroll
            for (int o = 16; o > 0; o >>= 1)
                acc += __shfl_xor_sync(0xffffffffu, acc, o);
            if (lane == 0) {
                float r = (half == 0) ? 1.0f : sr[i];
                sr[i] = r / fmaf(r, acc, EPSF);
            }
        }
        __syncthreads();

        // ---- col step partials: P_j += r_i * h_ij over own rows
        const int buf = (half + 1) & 1;
        {
            const uint2* hp =
                (const uint2*)(g_h + row0 * (MM / 2)) + tid;  // 4 cols/thread
            float4 acc = make_float4(0.f, 0.f, 0.f, 0.f);
#pragma unroll 8
            for (int i = 0; i < RPB; i++) {
                uint2 v = hp[(size_t)i * (MM / 4)];
                float rw = sr[i];
                float2 f0 = __half22float2(*(__half2*)&v.x);
                float2 f1 = __half22float2(*(__half2*)&v.y);
                acc.x = fmaf(rw, f0.x, acc.x);
                acc.y = fmaf(rw, f0.y, acc.y);
                acc.z = fmaf(rw, f1.x, acc.z);
                acc.w = fmaf(rw, f1.y, acc.w);
            }
            *(float4*)&g_part[buf][((size_t)(b * KB_ + k)) * MM + tid * 4] =
                acc;
        }
        batch_barrier(b, nextv);

        // ---- reduce partials -> c update (all blocks, identical order)
        {
            const int j = tid * 4;
            float4 p = make_float4(0.f, 0.f, 0.f, 0.f);
#pragma unroll
            for (int q = 0; q < KB_; q++) {
                const float4 v = __ldcg((const float4*)
                    &g_part[buf][((size_t)(b * KB_ + q)) * MM + j]);
                p.x += v.x; p.y += v.y; p.z += v.z; p.w += v.w;
            }
            float4 c = *(float4*)&sc[j];
            c.x = c.x / fmaf(c.x, p.x, EPSF);
            c.y = c.y / fmaf(c.y, p.y, EPSF);
            c.z = c.z / fmaf(c.z, p.z, EPSF);
            c.w = c.w / fmaf(c.w, p.w, EPSF);
            *(float4*)&sc[j] = c;
        }
        __syncthreads();
    }

    // ---------------- finalize: out = r_i * h_ij * c_j (fp16 copy, L2-hot)
    {
        const int j = tid * 4;
        const float4 c4 = *(float4*)&sc[j];
        const uint2* hp = (const uint2*)(g_h + row0 * (MM / 2)) + tid;
        float4* op = (float4*)(out + row0 * MM) + tid;
#pragma unroll 4
        for (int i = 0; i < RPB; i++) {
            const float r = sr[i];
            uint2 v = hp[(size_t)i * (MM / 4)];
            float2 f0 = __half22float2(*(__half2*)&v.x);
            float2 f1 = __half22float2(*(__half2*)&v.y);
            float4 o;
            o.x = r * f0.x * c4.x;
            o.y = r * f0.y * c4.y;
            o.z = r * f1.x * c4.z;
            o.w = r * f1.y * c4.w;
            op[(size_t)i * (MM / 4)] = o;
        }
    }
}

// ---------------------------------------------------------------------------
extern "C" void kernel_launch(void* const* d_in, const int* in_sizes, int n_in,
                              void* d_out, int out_size) {
    const float* s = (const float*)d_in[0];
    float* out = (float*)d_out;
    sinkhorn_kernel<<<BB * KB_, 256>>>(s, out);
}

// round 10
// speedup vs baseline: 1.1069x; 1.1069x over previous
#include <cuda_runtime.h>
#include <cuda_fp16.h>

// Sinkhorn on s[B=32, N=1024, M=1024], MAX_ITER=15, EPS=1e-4.
//
// Single persistent kernel. Factored form s_t = r_i * s0_ij * c_j.
// 512-thread blocks; block k of batch b owns rows [128k, 128k+128).
// Half 0 (tid<256) handles rows [0,64) of the slice, half 1 rows [64,128),
// each with R5's validated 64-row loop bodies; their column partials are
// combined through smem so each block emits ONE 4KB partial vector.
// 8 blocks per batch synchronize via a batch-local monotonic barrier.
// c is redundantly recomputed per block (split across halves) from the 8
// partials; r lives in smem. Finalize reads the fp16 copy (L2-hot).

#define BB 32
#define NN 1024
#define MM 1024
#define EPSF 1e-4f
#define KB_ 8             // blocks per batch
#define RPB (NN / KB_)    // 128 rows per block
#define HROWS 64          // rows per half
#define TPB 512

__device__ __half2 g_h[(size_t)BB * NN * MM / 2];   // 64 MB fp16 copy
__device__ float g_part[2][BB * KB_ * MM];          // double-buffered partials
__device__ int g_cnt2[BB];                          // zero-init
__device__ int g_flag[BB];                          // monotonic, persists

// ---------------------------------------------------------------------------
// Batch-local barrier: 8 blocks of batch b. Monotonic target continues from
// the persisted flag value, so graph replays need no reset.
__device__ __forceinline__ void batch_barrier(int b, int& nextv) {
    __threadfence();
    __syncthreads();
    nextv += 1;
    if (threadIdx.x == 0) {
        int old = atomicAdd(&g_cnt2[b], 1);
        if (old == KB_ - 1) {
            atomicExch(&g_cnt2[b], 0);
            __threadfence();
            *(volatile int*)&g_flag[b] = nextv;
        } else {
            while (*(volatile int*)&g_flag[b] - nextv < 0) __nanosleep(32);
        }
        __threadfence();
    }
    __syncthreads();
}

// ---------------------------------------------------------------------------
__global__ void __launch_bounds__(TPB, 2)
sinkhorn_kernel(const float* __restrict__ s, float* __restrict__ out) {
    const int bx = blockIdx.x;
    const int b = bx >> 3;         // batch
    const int k = bx & (KB_ - 1);  // block within batch
    const int tid = threadIdx.x;
    const int half = tid >> 8;     // 0 or 1
    const int ct = tid & 255;      // column group: owns cols [4ct, 4ct+4)

    __shared__ float sc[MM];       // column scaling c (full vector)
    __shared__ float sr[RPB];      // row scaling r (own 128 rows)
    __shared__ float scomb[MM];    // half-combine buffer (4 KB)

    int nextv = *(volatile int*)&g_flag[b];  // barrier base

    // this half's first row (global)
    const size_t hrow0 = (size_t)(b * NN + k * RPB + half * HROWS);

    // ---------------- it = 0: fp32->fp16 conversion + column partials (r=1)
    {
        const float4* sp = (const float4*)(s + hrow0 * MM) + ct;
        __half2* hp = g_h + hrow0 * (MM / 2) + ct * 2;
        float4 acc = make_float4(0.f, 0.f, 0.f, 0.f);
#pragma unroll 4
        for (int i = 0; i < HROWS; i++) {
            float4 v = sp[(size_t)i * (MM / 4)];
            __half2 h0 = __floats2half2_rn(v.x, v.y);
            __half2 h1 = __floats2half2_rn(v.z, v.w);
            uint2 o;
            o.x = *(unsigned*)&h0;
            o.y = *(unsigned*)&h1;
            *(uint2*)(hp + (size_t)i * (MM / 2)) = o;
            acc.x += v.x; acc.y += v.y; acc.z += v.z; acc.w += v.w;
        }
        if (half) *(float4*)&scomb[ct * 4] = acc;
        __syncthreads();
        if (!half) {
            float4 o2 = *(float4*)&scomb[ct * 4];
            acc.x += o2.x; acc.y += o2.y; acc.z += o2.z; acc.w += o2.w;
            *(float4*)&g_part[0][((size_t)(b * KB_ + k)) * MM + ct * 4] = acc;
        }
    }
    batch_barrier(b, nextv);

    // c init (c_old = 1): split reduce across halves; half1 sums q=4..7.
    {
        const int j = ct * 4;
        float4 p = make_float4(0.f, 0.f, 0.f, 0.f);
#pragma unroll
        for (int q = 0; q < KB_ / 2; q++) {
            const int qq = half * (KB_ / 2) + q;
            const float4 v = __ldcg(
                (const float4*)&g_part[0][((size_t)(b * KB_ + qq)) * MM + j]);
            p.x += v.x; p.y += v.y; p.z += v.z; p.w += v.w;
        }
        if (half) *(float4*)&scomb[j] = p;
        __syncthreads();
        if (!half) {
            float4 o2 = *(float4*)&scomb[j];
            p.x += o2.x; p.y += o2.y; p.z += o2.z; p.w += o2.w;
            sc[j + 0] = 1.0f / (p.x + EPSF);
            sc[j + 1] = 1.0f / (p.y + EPSF);
            sc[j + 2] = 1.0f / (p.z + EPSF);
            sc[j + 3] = 1.0f / (p.w + EPSF);
        }
    }
    __syncthreads();

    // ---------------- 7 x (row step it=2h+1, col step it=2h+2)
    const int warp = tid >> 5;     // 0..15
    const int lane = tid & 31;
    const size_t brow0 = (size_t)(b * NN + k * RPB);  // block's first row

    for (int hh = 0; hh < 7; hh++) {
        // ---- row step: warp w handles rows [8w, 8w+8) of the 128-row slice
#pragma unroll
        for (int rr = 0; rr < RPB / 16; rr++) {   // 8 rows per warp
            const int i = warp * (RPB / 16) + rr;
            const uint4* hp = (const uint4*)(g_h + (brow0 + i) * (MM / 2));
            float acc = 0.f;
#pragma unroll
            for (int kk = 0; kk < 4; kk++) {
                int v4 = kk * 32 + lane;
                uint4 v = hp[v4];
                int jj = v4 * 8;
                float2 f0 = __half22float2(*(__half2*)&v.x);
                float2 f1 = __half22float2(*(__half2*)&v.y);
                float2 f2 = __half22float2(*(__half2*)&v.z);
                float2 f3 = __half22float2(*(__half2*)&v.w);
                acc = fmaf(f0.x, sc[jj + 0], acc);
                acc = fmaf(f0.y, sc[jj + 1], acc);
                acc = fmaf(f1.x, sc[jj + 2], acc);
                acc = fmaf(f1.y, sc[jj + 3], acc);
                acc = fmaf(f2.x, sc[jj + 4], acc);
                acc = fmaf(f2.y, sc[jj + 5], acc);
                acc = fmaf(f3.x, sc[jj + 6], acc);
                acc = fmaf(f3.y, sc[jj + 7], acc);
            }
#pragma unroll
            for (int o = 16; o > 0; o >>= 1)
                acc += __shfl_xor_sync(0xffffffffu, acc, o);
            if (lane == 0) {
                float r = (hh == 0) ? 1.0f : sr[i];
                sr[i] = r / fmaf(r, acc, EPSF);
            }
        }
        __syncthreads();

        // ---- col step partials: P_j += r_i * h_ij over this half's 64 rows
        const int buf = (hh + 1) & 1;
        {
            const uint2* hp = (const uint2*)(g_h + hrow0 * (MM / 2)) + ct;
            const float* srh = sr + half * HROWS;
            float4 acc = make_float4(0.f, 0.f, 0.f, 0.f);
#pragma unroll 8
            for (int i = 0; i < HROWS; i++) {
                uint2 v = hp[(size_t)i * (MM / 4)];
                float rw = srh[i];
                float2 f0 = __half22float2(*(__half2*)&v.x);
                float2 f1 = __half22float2(*(__half2*)&v.y);
                acc.x = fmaf(rw, f0.x, acc.x);
                acc.y = fmaf(rw, f0.y, acc.y);
                acc.z = fmaf(rw, f1.x, acc.z);
                acc.w = fmaf(rw, f1.y, acc.w);
            }
            if (half) *(float4*)&scomb[ct * 4] = acc;
            __syncthreads();
            if (!half) {
                float4 o2 = *(float4*)&scomb[ct * 4];
                acc.x += o2.x; acc.y += o2.y; acc.z += o2.z; acc.w += o2.w;
                *(float4*)&g_part[buf][((size_t)(b * KB_ + k)) * MM + ct * 4] =
                    acc;
            }
        }
        batch_barrier(b, nextv);

        // ---- reduce partials -> c update (per block; split across halves)
        {
            const int j = ct * 4;
            float4 p = make_float4(0.f, 0.f, 0.f, 0.f);
#pragma unroll
            for (int q = 0; q < KB_ / 2; q++) {
                const int qq = half * (KB_ / 2) + q;
                const float4 v = __ldcg((const float4*)
                    &g_part[buf][((size_t)(b * KB_ + qq)) * MM + j]);
                p.x += v.x; p.y += v.y; p.z += v.z; p.w += v.w;
            }
            if (half) *(float4*)&scomb[j] = p;
            __syncthreads();
            if (!half) {
                float4 o2 = *(float4*)&scomb[j];
                p.x += o2.x; p.y += o2.y; p.z += o2.z; p.w += o2.w;
                float4 c = *(float4*)&sc[j];
                c.x = c.x / fmaf(c.x, p.x, EPSF);
                c.y = c.y / fmaf(c.y, p.y, EPSF);
                c.z = c.z / fmaf(c.z, p.z, EPSF);
                c.w = c.w / fmaf(c.w, p.w, EPSF);
                *(float4*)&sc[j] = c;
            }
        }
        __syncthreads();
    }

    // ---------------- finalize: out = r_i * h_ij * c_j (fp16 copy, L2-hot)
    {
        const int j = ct * 4;
        const float4 c4 = *(float4*)&sc[j];
        const float* srh = sr + half * HROWS;
        const uint2* hp = (const uint2*)(g_h + hrow0 * (MM / 2)) + ct;
        float4* op = (float4*)(out + hrow0 * MM) + ct;
#pragma unroll 4
        for (int i = 0; i < HROWS; i++) {
            const float r = srh[i];
            uint2 v = hp[(size_t)i * (MM / 4)];
            float2 f0 = __half22float2(*(__half2*)&v.x);
            float2 f1 = __half22float2(*(__half2*)&v.y);
            float4 o;
            o.x = r * f0.x * c4.x;
            o.y = r * f0.y * c4.y;
            o.z = r * f1.x * c4.z;
            o.w = r * f1.y * c4.w;
            op[(size_t)i * (MM / 4)] = o;
        }
    }
}

// ---------------------------------------------------------------------------
extern "C" void kernel_launch(void* const* d_in, const int* in_sizes, int n_in,
                              void* d_out, int out_size) {
    const float* s = (const float*)d_in[0];
    float* out = (float*)d_out;
    sinkhorn_kernel<<<BB * KB_, TPB>>>(s, out);
}